// round 6
// baseline (speedup 1.0000x reference)
#include <cuda_runtime.h>
#include <math.h>

#define N_ENT 200000
#define N_USR 100000
#define DIM   64
#define E_N   1500000
#define NI_N  1000000
#define N_RELM1 10
#define HALF_D 32   // float2 lanes per row
#define WPB  8      // warps per block
#define EBLK ((N_ENT + WPB - 1) / WPB)   // 25000
#define UBLK ((N_USR + WPB - 1) / WPB)   // 12500

// ---------------- device scratch (no allocation allowed) ----------------
__device__ int   g_remap[16];
__device__ int   g_cnt_ent[N_ENT];
__device__ int   g_off_ent[N_ENT + 1];
__device__ int   g_cnt_usr[N_USR];
__device__ int   g_off_usr[N_USR + 1];
__device__ int   g_packed[E_N];      // tail | (virt<<18)
__device__ int   g_items[NI_N];
__device__ float g_entB[N_ENT * DIM];
__device__ float g_usrB[N_USR * DIM];

// ---------------- helpers ----------------
__device__ __forceinline__ float wsum(float v) {
    #pragma unroll
    for (int o = 16; o > 0; o >>= 1) v += __shfl_xor_sync(0xffffffffu, v, o);
    return v;
}

__device__ __forceinline__ float2 squash_add(float2 acc, float den, float2 base) {
    float x = acc.x / den, y = acc.y / den;
    float sq = wsum(x * x + y * y);
    float nrm = sqrtf(sq);
    float s = (sq / (sq + 1.0f)) / fmaxf(nrm, 1e-12f);
    return make_float2(x * s + base.x, y * s + base.y);
}

// ---------------- preprocessing (4 launches total) ----------------

// L0: zero both count arrays + relation remap (256 threads/block, bounded)
__global__ void __launch_bounds__(256) init_k(const float* __restrict__ relw,
                                              const float* __restrict__ lat) {
    int i = blockIdx.x * blockDim.x + threadIdx.x;
    int total = N_ENT + N_USR;
    for (int j = i; j < total; j += gridDim.x * blockDim.x) {
        if (j < N_ENT) g_cnt_ent[j] = 0; else g_cnt_usr[j - N_ENT] = 0;
    }
    if (i < N_RELM1) {
        float best = -1e30f; int bi = 0;
        for (int v = 0; v < 3; v++) {
            float s = 0.f;
            #pragma unroll 4
            for (int k = 0; k < DIM; k++) s += relw[i * DIM + k] * lat[v * DIM + k];
            if (s > best) { best = s; bi = v; }
        }
        g_remap[i] = bi;
    }
}

// L1: histogram of entity heads and users in one kernel
__global__ void __launch_bounds__(256)
hist_both_k(const int* __restrict__ heads, const int* __restrict__ uidx) {
    int total = E_N + NI_N;
    for (int i = blockIdx.x * blockDim.x + threadIdx.x; i < total; i += gridDim.x * blockDim.x) {
        if (i < E_N) atomicAdd(&g_cnt_ent[heads[i]], 1);
        else         atomicAdd(&g_cnt_usr[uidx[i - E_N]], 1);
    }
}

// L2: one block per array — exclusive scan into off[], re-zero cnt[] (cursor for scatter)
__global__ void __launch_bounds__(1024) scan_both_k() {
    int *cnt, *off; int n;
    if (blockIdx.x == 0) { cnt = g_cnt_ent; off = g_off_ent; n = N_ENT; }
    else                 { cnt = g_cnt_usr; off = g_off_usr; n = N_USR; }
    const int tid = threadIdx.x;
    const int lane = tid & 31, wid = tid >> 5;
    __shared__ int wsh[32];
    __shared__ int carry_s;
    if (tid == 0) carry_s = 0;
    __syncthreads();
    for (int base = 0; base < n; base += 1024) {
        int i = base + tid;
        int v = (i < n) ? cnt[i] : 0;
        int x = v;
        #pragma unroll
        for (int o = 1; o < 32; o <<= 1) {
            int t = __shfl_up_sync(0xffffffffu, x, o);
            if (lane >= o) x += t;
        }
        if (lane == 31) wsh[wid] = x;
        __syncthreads();
        if (wid == 0) {
            int y = wsh[lane];
            #pragma unroll
            for (int o = 1; o < 32; o <<= 1) {
                int t = __shfl_up_sync(0xffffffffu, y, o);
                if (lane >= o) y += t;
            }
            wsh[lane] = y;
        }
        __syncthreads();
        int warp_off = (wid > 0) ? wsh[wid - 1] : 0;
        int incl = x + warp_off;
        int carry = carry_s;
        if (i < n) { off[i] = carry + incl - v; cnt[i] = 0; }
        __syncthreads();
        if (tid == 1023) carry_s = carry + incl;   // block total
        __syncthreads();
    }
    if (tid == 0) off[n] = carry_s;
}

// L3: scatter edges (packed tail|virt) and user items into CSR order
__global__ void __launch_bounds__(256)
scatter_both_k(const int* __restrict__ heads, const int* __restrict__ tails,
               const int* __restrict__ et,
               const int* __restrict__ uidx, const int* __restrict__ iidx) {
    int total = E_N + NI_N;
    for (int i = blockIdx.x * blockDim.x + threadIdx.x; i < total; i += gridDim.x * blockDim.x) {
        if (i < E_N) {
            int h = heads[i];
            int pos = g_off_ent[h] + atomicAdd(&g_cnt_ent[h], 1);
            int v = g_remap[et[i] - 1];
            g_packed[pos] = tails[i] | (v << 18);
        } else {
            int k = i - E_N;
            int u = uidx[k];
            int pos = g_off_usr[u] + atomicAdd(&g_cnt_usr[u], 1);
            g_items[pos] = iidx[k];
        }
    }
}

// ---------------- fused hop kernel: entity blocks + user blocks ----------------
#define CH 8   // edge chunk (ILP width)

__global__ void __launch_bounds__(256)
fused_hop_k(const float2* __restrict__ ent_in, const float2* __restrict__ usr_in,
            const float* __restrict__ aggw, int hop, int init,
            const int* __restrict__ off_e, const int* __restrict__ packed,
            const int* __restrict__ off_u, const int* __restrict__ items,
            float2* __restrict__ ent_store, float2* __restrict__ usr_store,
            float2* __restrict__ res_ent, float2* __restrict__ res_usr)
{
    __shared__ float s_d[WPB][32];     // pass-1 dots, first 32 edges per head

    const int wid  = threadIdx.x >> 5;
    const int lane = threadIdx.x & 31;
    float* __restrict__ sd = s_d[wid];

    if (blockIdx.x < EBLK) {
        // ======================= ENTITY =======================
        int w = blockIdx.x * WPB + wid;
        if (w >= N_ENT) return;

        float2 en = ent_in[w * HALF_D + lane];
        int s = off_e[w], e = off_e[w + 1];

        float a0 = aggw[hop * 3 + 0], a1 = aggw[hop * 3 + 1], a2 = aggw[hop * 3 + 2];
        float mx = fmaxf(a0, fmaxf(a1, a2));
        float e0 = expf(a0 - mx), e1 = expf(a1 - mx), e2 = expf(a2 - mx);
        float inv = 1.0f / (e0 + e1 + e2);
        float w0 = e0 * inv, w1 = e1 * inv, w2 = e2 * inv;

        // ---- pass 0: plain per-virt sums (8-wide MLP) ----
        float2 A0 = {0, 0}, A1 = {0, 0}, A2 = {0, 0};
        int c0 = 0, c1 = 0, c2 = 0;
        for (int base = s; base < e; base += 32) {
            int m = min(32, e - base);
            int pk = (lane < m) ? packed[base + lane] : 0;
            for (int c = 0; c < m; c += CH) {
                int cm = min(CH, m - c);
                float2 r[CH]; int vv[CH];
                #pragma unroll
                for (int q = 0; q < CH; q++) {
                    int pm = __shfl_sync(0xffffffffu, pk, c + q);
                    vv[q] = pm >> 18;
                    r[q] = ent_in[(pm & 0x3FFFF) * HALF_D + lane];
                }
                #pragma unroll
                for (int q = 0; q < CH; q++) {
                    if (q < cm) {
                        if (vv[q] == 0)      { A0.x += r[q].x; A0.y += r[q].y; c0++; }
                        else if (vv[q] == 1) { A1.x += r[q].x; A1.y += r[q].y; c1++; }
                        else                 { A2.x += r[q].x; A2.y += r[q].y; c2++; }
                    }
                }
            }
        }
        float d0 = fmaxf((float)c0, 1.f), d1 = fmaxf((float)c1, 1.f), d2 = fmaxf((float)c2, 1.f);
        float2 u10 = squash_add(A0, d0, en);
        float2 u11 = squash_add(A1, d1, en);
        float2 u12 = squash_add(A2, d2, en);

        // ---- pass 1: sim-weighted; batch butterflies 8-wide; cache dots in sd ----
        A0 = make_float2(0, 0); A1 = make_float2(0, 0); A2 = make_float2(0, 0);
        for (int base = s; base < e; base += 32) {
            int m = min(32, e - base);
            int pk = (lane < m) ? packed[base + lane] : 0;
            bool first = (base == s);
            for (int c = 0; c < m; c += CH) {
                int cm = min(CH, m - c);
                float2 r[CH]; int vv[CH]; float p[CH];
                #pragma unroll
                for (int q = 0; q < CH; q++) {
                    int pm = __shfl_sync(0xffffffffu, pk, c + q);
                    vv[q] = pm >> 18;
                    r[q] = ent_in[(pm & 0x3FFFF) * HALF_D + lane];
                    float2 uv = (vv[q] == 0) ? u10 : ((vv[q] == 1) ? u11 : u12);
                    p[q] = uv.x * r[q].x + uv.y * r[q].y;
                }
                #pragma unroll
                for (int o = 16; o > 0; o >>= 1)
                    #pragma unroll
                    for (int q = 0; q < CH; q++)
                        p[q] += __shfl_xor_sync(0xffffffffu, p[q], o);
                #pragma unroll
                for (int q = 0; q < CH; q++) {
                    if (q < cm) {
                        if (first && lane == 0) sd[c + q] = p[q];
                        float d = p[q];
                        if (vv[q] == 0)      { A0.x += d * r[q].x; A0.y += d * r[q].y; }
                        else if (vv[q] == 1) { A1.x += d * r[q].x; A1.y += d * r[q].y; }
                        else                 { A2.x += d * r[q].x; A2.y += d * r[q].y; }
                    }
                }
            }
        }
        float2 u20 = squash_add(A0, d0, en);
        float2 u21 = squash_add(A1, d1, en);
        float2 u22 = squash_add(A2, d2, en);

        __syncwarp();

        // ---- pass 2: scale = d1^2 * d2 ----
        A0 = make_float2(0, 0); A1 = make_float2(0, 0); A2 = make_float2(0, 0);
        for (int base = s; base < e; base += 32) {
            int m = min(32, e - base);
            int pk = (lane < m) ? packed[base + lane] : 0;
            bool first = (base == s);
            for (int c = 0; c < m; c += CH) {
                int cm = min(CH, m - c);
                float2 r[CH]; int vv[CH]; float pb[CH];
                #pragma unroll
                for (int q = 0; q < CH; q++) {
                    int pm = __shfl_sync(0xffffffffu, pk, c + q);
                    vv[q] = pm >> 18;
                    r[q] = ent_in[(pm & 0x3FFFF) * HALF_D + lane];
                    float2 uB = (vv[q] == 0) ? u20 : ((vv[q] == 1) ? u21 : u22);
                    pb[q] = uB.x * r[q].x + uB.y * r[q].y;
                }
                if (first) {
                    #pragma unroll
                    for (int o = 16; o > 0; o >>= 1)
                        #pragma unroll
                        for (int q = 0; q < CH; q++)
                            pb[q] += __shfl_xor_sync(0xffffffffu, pb[q], o);
                    #pragma unroll
                    for (int q = 0; q < CH; q++) {
                        if (q < cm) {
                            float pa = sd[c + q];
                            float sc = pa * pa * pb[q];
                            if (vv[q] == 0)      { A0.x += sc * r[q].x; A0.y += sc * r[q].y; }
                            else if (vv[q] == 1) { A1.x += sc * r[q].x; A1.y += sc * r[q].y; }
                            else                 { A2.x += sc * r[q].x; A2.y += sc * r[q].y; }
                        }
                    }
                } else {
                    float pa[CH];
                    #pragma unroll
                    for (int q = 0; q < CH; q++) {
                        float2 uA = (vv[q] == 0) ? u10 : ((vv[q] == 1) ? u11 : u12);
                        pa[q] = uA.x * r[q].x + uA.y * r[q].y;
                    }
                    #pragma unroll
                    for (int o = 16; o > 0; o >>= 1)
                        #pragma unroll
                        for (int q = 0; q < CH; q++) {
                            pb[q] += __shfl_xor_sync(0xffffffffu, pb[q], o);
                            pa[q] += __shfl_xor_sync(0xffffffffu, pa[q], o);
                        }
                    #pragma unroll
                    for (int q = 0; q < CH; q++) {
                        if (q < cm) {
                            float sc = pa[q] * pa[q] * pb[q];
                            if (vv[q] == 0)      { A0.x += sc * r[q].x; A0.y += sc * r[q].y; }
                            else if (vv[q] == 1) { A1.x += sc * r[q].x; A1.y += sc * r[q].y; }
                            else                 { A2.x += sc * r[q].x; A2.y += sc * r[q].y; }
                        }
                    }
                }
            }
        }
        float2 u30 = make_float2(A0.x / d0 + en.x, A0.y / d0 + en.y);
        float2 u31 = make_float2(A1.x / d1 + en.x, A1.y / d1 + en.y);
        float2 u32 = make_float2(A2.x / d2 + en.x, A2.y / d2 + en.y);

        float2 ag = make_float2(w0 * u30.x + w1 * u31.x + w2 * u32.x,
                                w0 * u30.y + w1 * u31.y + w2 * u32.y);
        float sq = wsum(ag.x * ag.x + ag.y * ag.y);
        float in2 = 1.0f / fmaxf(sqrtf(sq), 1e-12f);
        float2 o = make_float2(ag.x * in2, ag.y * in2);
        if (ent_store) ent_store[w * HALF_D + lane] = o;
        float2 r;
        if (init) { r.x = en.x + o.x; r.y = en.y + o.y; }
        else { r = res_ent[w * HALF_D + lane]; r.x += o.x; r.y += o.y; }
        res_ent[w * HALF_D + lane] = r;

    } else {
        // ======================= USER =======================
        int w = (blockIdx.x - EBLK) * WPB + wid;
        if (w >= N_USR) return;

        float2 un = usr_in[w * HALF_D + lane];
        int s = off_u[w], e = off_u[w + 1];
        float den = fmaxf((float)(e - s), 1.f);

        // it0: plain sum
        float2 A = {0, 0};
        for (int base = s; base < e; base += 32) {
            int m = min(32, e - base);
            int it = (lane < m) ? items[base + lane] : 0;
            for (int c = 0; c < m; c += CH) {
                int cm = min(CH, m - c);
                float2 r[CH];
                #pragma unroll
                for (int q = 0; q < CH; q++) {
                    int t = __shfl_sync(0xffffffffu, it, c + q);
                    r[q] = ent_in[t * HALF_D + lane];
                }
                #pragma unroll
                for (int q = 0; q < CH; q++)
                    if (q < cm) { A.x += r[q].x; A.y += r[q].y; }
            }
        }
        float2 u1 = squash_add(A, den, un);

        // it1: sim with u1
        A = make_float2(0, 0);
        for (int base = s; base < e; base += 32) {
            int m = min(32, e - base);
            int it = (lane < m) ? items[base + lane] : 0;
            for (int c = 0; c < m; c += CH) {
                int cm = min(CH, m - c);
                float2 r[CH]; float p[CH];
                #pragma unroll
                for (int q = 0; q < CH; q++) {
                    int t = __shfl_sync(0xffffffffu, it, c + q);
                    r[q] = ent_in[t * HALF_D + lane];
                    p[q] = u1.x * r[q].x + u1.y * r[q].y;
                }
                #pragma unroll
                for (int o = 16; o > 0; o >>= 1)
                    #pragma unroll
                    for (int q = 0; q < CH; q++)
                        p[q] += __shfl_xor_sync(0xffffffffu, p[q], o);
                #pragma unroll
                for (int q = 0; q < CH; q++)
                    if (q < cm) { A.x += p[q] * r[q].x; A.y += p[q] * r[q].y; }
            }
        }
        float2 u2 = squash_add(A, den, un);

        // it2: sim with u2 (no squash)
        A = make_float2(0, 0);
        for (int base = s; base < e; base += 32) {
            int m = min(32, e - base);
            int it = (lane < m) ? items[base + lane] : 0;
            for (int c = 0; c < m; c += CH) {
                int cm = min(CH, m - c);
                float2 r[CH]; float p[CH];
                #pragma unroll
                for (int q = 0; q < CH; q++) {
                    int t = __shfl_sync(0xffffffffu, it, c + q);
                    r[q] = ent_in[t * HALF_D + lane];
                    p[q] = u2.x * r[q].x + u2.y * r[q].y;
                }
                #pragma unroll
                for (int o = 16; o > 0; o >>= 1)
                    #pragma unroll
                    for (int q = 0; q < CH; q++)
                        p[q] += __shfl_xor_sync(0xffffffffu, p[q], o);
                #pragma unroll
                for (int q = 0; q < CH; q++)
                    if (q < cm) { A.x += p[q] * r[q].x; A.y += p[q] * r[q].y; }
            }
        }
        float2 u3 = make_float2(A.x / den + un.x, A.y / den + un.y);

        float sq = wsum(u3.x * u3.x + u3.y * u3.y);
        float in2 = 1.0f / fmaxf(sqrtf(sq), 1e-12f);
        float2 o = make_float2(u3.x * in2, u3.y * in2);
        if (usr_store) usr_store[w * HALF_D + lane] = o;
        float2 r;
        if (init) { r.x = un.x + o.x; r.y = un.y + o.y; }
        else { r = res_usr[w * HALF_D + lane]; r.x += o.x; r.y += o.y; }
        res_usr[w * HALF_D + lane] = r;
    }
}

// ---------------- launch (6 launches; fused hops are #4 and #5) ----------------
extern "C" void kernel_launch(void* const* d_in, const int* in_sizes, int n_in,
                              void* d_out, int out_size) {
    const float* entity_emb = (const float*)d_in[0];
    const float* user_emb   = (const float*)d_in[1];
    const float* latent     = (const float*)d_in[2];
    const float* relw       = (const float*)d_in[3];
    const float* aggw       = (const float*)d_in[4];
    const int*   eidx       = (const int*)d_in[5];   // [2,E]: head row, then tail row
    const int*   etype      = (const int*)d_in[6];
    const int*   uidx       = (const int*)d_in[7];
    const int*   iidx       = (const int*)d_in[8];
    float* out = (float*)d_out;

    int *p_off_ent, *p_off_usr, *p_packed, *p_items;
    float *p_entB, *p_usrB;
    cudaGetSymbolAddress((void**)&p_off_ent, g_off_ent);
    cudaGetSymbolAddress((void**)&p_off_usr, g_off_usr);
    cudaGetSymbolAddress((void**)&p_packed,  g_packed);
    cudaGetSymbolAddress((void**)&p_items,   g_items);
    cudaGetSymbolAddress((void**)&p_entB,    g_entB);
    cudaGetSymbolAddress((void**)&p_usrB,    g_usrB);

    init_k<<<(N_ENT + N_USR + 255) / 256, 256>>>(relw, latent);              // #0
    hist_both_k<<<2048, 256>>>(eidx, uidx);                                  // #1
    scan_both_k<<<2, 1024>>>();                                              // #2
    scatter_both_k<<<2048, 256>>>(eidx, eidx + E_N, etype, uidx, iidx);      // #3

    float2* res_e = (float2*)out;
    float2* res_u = (float2*)(out + (size_t)N_ENT * DIM);

    // hop 0 (#4): base embeddings in; init residual in-kernel; store hop output
    fused_hop_k<<<EBLK + UBLK, 256>>>(
        (const float2*)entity_emb, (const float2*)user_emb, aggw, 0, 1,
        p_off_ent, p_packed, p_off_usr, p_items,
        (float2*)p_entB, (float2*)p_usrB, res_e, res_u);

    // hop 1 (#5): hop-0 outputs in; accumulate residual only  <-- ncu -s 5 lands here
    fused_hop_k<<<EBLK + UBLK, 256>>>(
        (const float2*)p_entB, (const float2*)p_usrB, aggw, 1, 0,
        p_off_ent, p_packed, p_off_usr, p_items,
        nullptr, nullptr, res_e, res_u);
}

// round 7
// speedup vs baseline: 1.2951x; 1.2951x over previous
#include <cuda_runtime.h>
#include <math.h>

#define N_ENT 200000
#define N_USR 100000
#define DIM   64
#define E_N   1500000
#define NI_N  1000000
#define N_RELM1 10
#define HALF_D 32   // float2 lanes per row
#define WPB  8      // warps per block
#define EBLK ((N_ENT + WPB - 1) / WPB)   // 25000
#define UBLK ((N_USR + WPB - 1) / WPB)   // 12500
#define ZBLK 512                          // cnt-rezero blocks appended to hop0 grid

// ---------------- device scratch (no allocation allowed) ----------------
// NOTE: __device__ globals are zero-initialized at module load. The kernels
// maintain the invariant that g_cnt_* are all-zero at entry to kernel_launch
// (hop0's tail blocks re-zero them after scatter), so no init launch needed.
__device__ int   g_remap[16];
__device__ int   g_cnt_ent[N_ENT];
__device__ int   g_off_ent[N_ENT + 1];
__device__ int   g_cnt_usr[N_USR];
__device__ int   g_off_usr[N_USR + 1];
__device__ int   g_packed[E_N];      // tail | (virt<<18)
__device__ int   g_items[NI_N];
__device__ float g_entB[N_ENT * DIM];
__device__ float g_usrB[N_USR * DIM];

// ---------------- helpers ----------------
__device__ __forceinline__ float wsum(float v) {
    #pragma unroll
    for (int o = 16; o > 0; o >>= 1) v += __shfl_xor_sync(0xffffffffu, v, o);
    return v;
}

__device__ __forceinline__ float2 squash_add(float2 acc, float den, float2 base) {
    float x = acc.x / den, y = acc.y / den;
    float sq = wsum(x * x + y * y);
    float nrm = sqrtf(sq);
    float s = (sq / (sq + 1.0f)) / fmaxf(nrm, 1e-12f);
    return make_float2(x * s + base.x, y * s + base.y);
}

// ---------------- preprocessing (3 launches total) ----------------

// L0: histogram heads + users (cnt arrays are zero at entry, see invariant);
//     first 10 threads of block 0 also compute the relation remap.
__global__ void __launch_bounds__(256)
hist_both_k(const int* __restrict__ heads, const int* __restrict__ uidx,
            const float* __restrict__ relw, const float* __restrict__ lat) {
    int gi = blockIdx.x * blockDim.x + threadIdx.x;
    if (gi < N_RELM1) {
        float best = -1e30f; int bi = 0;
        for (int v = 0; v < 3; v++) {
            float sdot = 0.f;
            #pragma unroll 1
            for (int k = 0; k < DIM; k++) sdot += relw[gi * DIM + k] * lat[v * DIM + k];
            if (sdot > best) { best = sdot; bi = v; }
        }
        g_remap[gi] = bi;
    }
    int total = E_N + NI_N;
    for (int i = gi; i < total; i += gridDim.x * blockDim.x) {
        if (i < E_N) atomicAdd(&g_cnt_ent[heads[i]], 1);
        else         atomicAdd(&g_cnt_usr[uidx[i - E_N]], 1);
    }
}

// L1: one block per array — exclusive scan into off[], re-zero cnt[] (cursor for scatter)
__global__ void __launch_bounds__(1024) scan_both_k() {
    int *cnt, *off; int n;
    if (blockIdx.x == 0) { cnt = g_cnt_ent; off = g_off_ent; n = N_ENT; }
    else                 { cnt = g_cnt_usr; off = g_off_usr; n = N_USR; }
    const int tid = threadIdx.x;
    const int lane = tid & 31, wid = tid >> 5;
    __shared__ int wsh[32];
    __shared__ int carry_s;
    if (tid == 0) carry_s = 0;
    __syncthreads();
    for (int base = 0; base < n; base += 1024) {
        int i = base + tid;
        int v = (i < n) ? cnt[i] : 0;
        int x = v;
        #pragma unroll
        for (int o = 1; o < 32; o <<= 1) {
            int t = __shfl_up_sync(0xffffffffu, x, o);
            if (lane >= o) x += t;
        }
        if (lane == 31) wsh[wid] = x;
        __syncthreads();
        if (wid == 0) {
            int y = wsh[lane];
            #pragma unroll
            for (int o = 1; o < 32; o <<= 1) {
                int t = __shfl_up_sync(0xffffffffu, y, o);
                if (lane >= o) y += t;
            }
            wsh[lane] = y;
        }
        __syncthreads();
        int warp_off = (wid > 0) ? wsh[wid - 1] : 0;
        int incl = x + warp_off;
        int carry = carry_s;
        if (i < n) { off[i] = carry + incl - v; cnt[i] = 0; }
        __syncthreads();
        if (tid == 1023) carry_s = carry + incl;   // block total
        __syncthreads();
    }
    if (tid == 0) off[n] = carry_s;
}

// L2: scatter edges (packed tail|virt) and user items into CSR order
__global__ void __launch_bounds__(256)
scatter_both_k(const int* __restrict__ heads, const int* __restrict__ tails,
               const int* __restrict__ et,
               const int* __restrict__ uidx, const int* __restrict__ iidx) {
    int total = E_N + NI_N;
    for (int i = blockIdx.x * blockDim.x + threadIdx.x; i < total; i += gridDim.x * blockDim.x) {
        if (i < E_N) {
            int h = heads[i];
            int pos = g_off_ent[h] + atomicAdd(&g_cnt_ent[h], 1);
            int v = g_remap[et[i] - 1];
            g_packed[pos] = tails[i] | (v << 18);
        } else {
            int k = i - E_N;
            int u = uidx[k];
            int pos = g_off_usr[u] + atomicAdd(&g_cnt_usr[u], 1);
            g_items[pos] = iidx[k];
        }
    }
}

// ---------------- fused hop kernel (R3 loop shape + sd dot-cache) ----------------
__global__ void __launch_bounds__(256)
fused_hop_k(const float2* __restrict__ ent_in, const float2* __restrict__ usr_in,
            const float* __restrict__ aggw, int hop, int init,
            const int* __restrict__ off_e, const int* __restrict__ packed,
            const int* __restrict__ off_u, const int* __restrict__ items,
            float2* __restrict__ ent_store, float2* __restrict__ usr_store,
            float2* __restrict__ res_ent, float2* __restrict__ res_usr)
{
    __shared__ float s_d[WPB][32];     // pass-1 dots, first 32 edges per head

    const int wid  = threadIdx.x >> 5;
    const int lane = threadIdx.x & 31;
    float* __restrict__ sd = s_d[wid];

    if (blockIdx.x >= EBLK + UBLK) {
        // cnt re-zero duty (hop0 only): restore the all-zero invariant for next call
        int i = (blockIdx.x - (EBLK + UBLK)) * 256 + threadIdx.x;
        for (; i < N_ENT + N_USR; i += ZBLK * 256) {
            if (i < N_ENT) g_cnt_ent[i] = 0;
            else           g_cnt_usr[i - N_ENT] = 0;
        }
        return;
    }

    if (blockIdx.x < EBLK) {
        // ======================= ENTITY =======================
        int w = blockIdx.x * WPB + wid;
        if (w >= N_ENT) return;

        float2 en = ent_in[w * HALF_D + lane];
        int s = off_e[w], e = off_e[w + 1];

        float a0 = aggw[hop * 3 + 0], a1 = aggw[hop * 3 + 1], a2 = aggw[hop * 3 + 2];
        float mx = fmaxf(a0, fmaxf(a1, a2));
        float e0 = expf(a0 - mx), e1 = expf(a1 - mx), e2 = expf(a2 - mx);
        float inv = 1.0f / (e0 + e1 + e2);
        float w0 = e0 * inv, w1 = e1 * inv, w2 = e2 * inv;

        // ---- pass 0: plain per-virt mean ----
        float2 A0 = {0, 0}, A1 = {0, 0}, A2 = {0, 0};
        int c0 = 0, c1 = 0, c2 = 0;
        for (int b = s; b < e; b += 32) {
            int m = min(32, e - b);
            int pk = (lane < m) ? packed[b + lane] : 0;
            for (int j = 0; j < m; j++) {
                int p = __shfl_sync(0xffffffffu, pk, j);
                int t = p & 0x3FFFF, v = p >> 18;
                float2 nt = ent_in[t * HALF_D + lane];
                if (v == 0)      { A0.x += nt.x; A0.y += nt.y; c0++; }
                else if (v == 1) { A1.x += nt.x; A1.y += nt.y; c1++; }
                else             { A2.x += nt.x; A2.y += nt.y; c2++; }
            }
        }
        float d0 = fmaxf((float)c0, 1.f), d1 = fmaxf((float)c1, 1.f), d2 = fmaxf((float)c2, 1.f);
        float2 u10 = squash_add(A0, d0, en);
        float2 u11 = squash_add(A1, d1, en);
        float2 u12 = squash_add(A2, d2, en);

        // ---- pass 1: sim-weighted; cache dots in sd (first 32 edges) ----
        A0 = make_float2(0, 0); A1 = make_float2(0, 0); A2 = make_float2(0, 0);
        for (int b = s; b < e; b += 32) {
            int m = min(32, e - b);
            int pk = (lane < m) ? packed[b + lane] : 0;
            bool first = (b == s);
            for (int j = 0; j < m; j++) {
                int p = __shfl_sync(0xffffffffu, pk, j);
                int t = p & 0x3FFFF, v = p >> 18;
                float2 nt = ent_in[t * HALF_D + lane];
                float2 uv = (v == 0) ? u10 : ((v == 1) ? u11 : u12);
                float d = wsum(uv.x * nt.x + uv.y * nt.y);
                if (first && lane == 0) sd[j] = d;
                if (v == 0)      { A0.x += d * nt.x; A0.y += d * nt.y; }
                else if (v == 1) { A1.x += d * nt.x; A1.y += d * nt.y; }
                else             { A2.x += d * nt.x; A2.y += d * nt.y; }
            }
        }
        float2 u20 = squash_add(A0, d0, en);
        float2 u21 = squash_add(A1, d1, en);
        float2 u22 = squash_add(A2, d2, en);

        __syncwarp();

        // ---- pass 2: scale = d1^2 * d2; first 32 edges reuse sd, tail recomputes ----
        A0 = make_float2(0, 0); A1 = make_float2(0, 0); A2 = make_float2(0, 0);
        for (int b = s; b < e; b += 32) {
            int m = min(32, e - b);
            int pk = (lane < m) ? packed[b + lane] : 0;
            bool first = (b == s);
            for (int j = 0; j < m; j++) {
                int p = __shfl_sync(0xffffffffu, pk, j);
                int t = p & 0x3FFFF, v = p >> 18;
                float2 nt = ent_in[t * HALF_D + lane];
                float2 uB = (v == 0) ? u20 : ((v == 1) ? u21 : u22);
                float pb = uB.x * nt.x + uB.y * nt.y;
                float pa;
                if (first) {
                    pb = wsum(pb);
                    pa = sd[j];
                } else {
                    float2 uA = (v == 0) ? u10 : ((v == 1) ? u11 : u12);
                    pa = uA.x * nt.x + uA.y * nt.y;
                    #pragma unroll
                    for (int o = 16; o > 0; o >>= 1) {
                        pa += __shfl_xor_sync(0xffffffffu, pa, o);
                        pb += __shfl_xor_sync(0xffffffffu, pb, o);
                    }
                }
                float sc = pa * pa * pb;
                if (v == 0)      { A0.x += sc * nt.x; A0.y += sc * nt.y; }
                else if (v == 1) { A1.x += sc * nt.x; A1.y += sc * nt.y; }
                else             { A2.x += sc * nt.x; A2.y += sc * nt.y; }
            }
        }
        float2 u30 = make_float2(A0.x / d0 + en.x, A0.y / d0 + en.y);
        float2 u31 = make_float2(A1.x / d1 + en.x, A1.y / d1 + en.y);
        float2 u32 = make_float2(A2.x / d2 + en.x, A2.y / d2 + en.y);

        float2 ag = make_float2(w0 * u30.x + w1 * u31.x + w2 * u32.x,
                                w0 * u30.y + w1 * u31.y + w2 * u32.y);
        float sq = wsum(ag.x * ag.x + ag.y * ag.y);
        float in2 = 1.0f / fmaxf(sqrtf(sq), 1e-12f);
        float2 o = make_float2(ag.x * in2, ag.y * in2);
        if (ent_store) ent_store[w * HALF_D + lane] = o;
        float2 r;
        if (init) { r.x = en.x + o.x; r.y = en.y + o.y; }
        else { r = res_ent[w * HALF_D + lane]; r.x += o.x; r.y += o.y; }
        res_ent[w * HALF_D + lane] = r;

    } else {
        // ======================= USER =======================
        int w = (blockIdx.x - EBLK) * WPB + wid;
        if (w >= N_USR) return;

        float2 un = usr_in[w * HALF_D + lane];
        int s = off_u[w], e = off_u[w + 1];
        float den = fmaxf((float)(e - s), 1.f);

        // it0
        float2 A = {0, 0};
        for (int b = s; b < e; b += 32) {
            int m = min(32, e - b);
            int it = (lane < m) ? items[b + lane] : 0;
            for (int j = 0; j < m; j++) {
                int t = __shfl_sync(0xffffffffu, it, j);
                float2 nt = ent_in[t * HALF_D + lane];
                A.x += nt.x; A.y += nt.y;
            }
        }
        float2 u1 = squash_add(A, den, un);

        // it1
        A = make_float2(0, 0);
        for (int b = s; b < e; b += 32) {
            int m = min(32, e - b);
            int it = (lane < m) ? items[b + lane] : 0;
            for (int j = 0; j < m; j++) {
                int t = __shfl_sync(0xffffffffu, it, j);
                float2 nt = ent_in[t * HALF_D + lane];
                float d = wsum(u1.x * nt.x + u1.y * nt.y);
                A.x += d * nt.x; A.y += d * nt.y;
            }
        }
        float2 u2 = squash_add(A, den, un);

        // it2 (no squash)
        A = make_float2(0, 0);
        for (int b = s; b < e; b += 32) {
            int m = min(32, e - b);
            int it = (lane < m) ? items[b + lane] : 0;
            for (int j = 0; j < m; j++) {
                int t = __shfl_sync(0xffffffffu, it, j);
                float2 nt = ent_in[t * HALF_D + lane];
                float d = wsum(u2.x * nt.x + u2.y * nt.y);
                A.x += d * nt.x; A.y += d * nt.y;
            }
        }
        float2 u3 = make_float2(A.x / den + un.x, A.y / den + un.y);

        float sq = wsum(u3.x * u3.x + u3.y * u3.y);
        float in2 = 1.0f / fmaxf(sqrtf(sq), 1e-12f);
        float2 o = make_float2(u3.x * in2, u3.y * in2);
        if (usr_store) usr_store[w * HALF_D + lane] = o;
        float2 r;
        if (init) { r.x = un.x + o.x; r.y = un.y + o.y; }
        else { r = res_usr[w * HALF_D + lane]; r.x += o.x; r.y += o.y; }
        res_usr[w * HALF_D + lane] = r;
    }
}

// ---------------- launch (5 launches; hop0 is launch #3 → ncu -s 5 hits it) ----------------
extern "C" void kernel_launch(void* const* d_in, const int* in_sizes, int n_in,
                              void* d_out, int out_size) {
    const float* entity_emb = (const float*)d_in[0];
    const float* user_emb   = (const float*)d_in[1];
    const float* latent     = (const float*)d_in[2];
    const float* relw       = (const float*)d_in[3];
    const float* aggw       = (const float*)d_in[4];
    const int*   eidx       = (const int*)d_in[5];   // [2,E]: head row, then tail row
    const int*   etype      = (const int*)d_in[6];
    const int*   uidx       = (const int*)d_in[7];
    const int*   iidx       = (const int*)d_in[8];
    float* out = (float*)d_out;

    int *p_off_ent, *p_off_usr, *p_packed, *p_items;
    float *p_entB, *p_usrB;
    cudaGetSymbolAddress((void**)&p_off_ent, g_off_ent);
    cudaGetSymbolAddress((void**)&p_off_usr, g_off_usr);
    cudaGetSymbolAddress((void**)&p_packed,  g_packed);
    cudaGetSymbolAddress((void**)&p_items,   g_items);
    cudaGetSymbolAddress((void**)&p_entB,    g_entB);
    cudaGetSymbolAddress((void**)&p_usrB,    g_usrB);

    hist_both_k<<<2048, 256>>>(eidx, uidx, relw, latent);                    // #0
    scan_both_k<<<2, 1024>>>();                                              // #1
    scatter_both_k<<<2048, 256>>>(eidx, eidx + E_N, etype, uidx, iidx);      // #2

    float2* res_e = (float2*)out;
    float2* res_u = (float2*)(out + (size_t)N_ENT * DIM);

    // hop 0 (#3): base embeddings in; init residual; extra ZBLK blocks re-zero cnt
    fused_hop_k<<<EBLK + UBLK + ZBLK, 256>>>(
        (const float2*)entity_emb, (const float2*)user_emb, aggw, 0, 1,
        p_off_ent, p_packed, p_off_usr, p_items,
        (float2*)p_entB, (float2*)p_usrB, res_e, res_u);

    // hop 1 (#4): hop-0 outputs in; accumulate residual only
    fused_hop_k<<<EBLK + UBLK, 256>>>(
        (const float2*)p_entB, (const float2*)p_usrB, aggw, 1, 0,
        p_off_ent, p_packed, p_off_usr, p_items,
        nullptr, nullptr, res_e, res_u);
}